// round 13
// baseline (speedup 1.0000x reference)
#include <cuda_runtime.h>
#include <cuda_fp16.h>

// ---------------------------------------------------------------------------
// TabM packed ensemble: out = mean_k( MLP_k(x) ), K=32 MLPs 512->1024^4->100.
// ptxas target is plain sm_103 (no 'a'): tcgen05 unavailable. Classic
// mma.sync.m16n8k16 FP16 (HMMA, fp32 accum) with cp.async 3-stage pipeline.
// fp16 chosen over bf16 for 8x lower rounding noise (rel_err 5.1e-3 -> ~6e-4).
// ---------------------------------------------------------------------------

#define DI static __device__ __forceinline__

constexpr int BB = 4096;   // batch
constexpr int FF = 512;    // in features
constexpr int HH = 1024;   // hidden
constexpr int CC = 100;    // classes
constexpr int KK = 32;     // ensemble
constexpr int NL = 3;      // hidden->hidden layers
constexpr int CPAD = 128;  // padded classes

// ---- device scratch (__device__ globals: the sanctioned no-alloc path) ----
__device__ __half g_xb[BB * FF];                // x in fp16
__device__ __half g_wt_in[KK * HH * FF];        // W_in^T  [k][h][f]  (K-major)
__device__ __half g_wt_hid[NL * KK * HH * HH];  // W_hid^T [i][k][j][h]
__device__ __half g_wt_out[KK * CPAD * HH];     // W_out^T [k][c_pad][h], zero-padded
__device__ float  g_bout_pad[KK * CPAD];
__device__ __half g_act0[KK * BB * HH];
__device__ __half g_act1[KK * BB * HH];
__device__ float  g_logits[KK * BB * CPAD];     // per-k fp32 logits (padded)

// ---------------------------------------------------------------------------
// PTX helpers (sm_80+ baseline ISA only)
// ---------------------------------------------------------------------------
DI unsigned smem_u32(const void* p) { return (unsigned)__cvta_generic_to_shared(p); }

DI void cpa16(unsigned dst, const void* src) {
    asm volatile("cp.async.cg.shared.global [%0], [%1], 16;"
                 ::"r"(dst), "l"(__cvta_generic_to_global(src)) : "memory");
}
DI void cpa_commit() { asm volatile("cp.async.commit_group;" ::: "memory"); }
template <int N>
DI void cpa_wait() { asm volatile("cp.async.wait_group %0;" ::"n"(N) : "memory"); }

DI unsigned swz(unsigned off) { return off ^ ((off >> 3) & 0x70); }  // SW128 / Swizzle<3,4,3>

DI void ldsm4(unsigned& r0, unsigned& r1, unsigned& r2, unsigned& r3, unsigned addr) {
    asm volatile("ldmatrix.sync.aligned.m8n8.x4.shared.b16 {%0,%1,%2,%3}, [%4];"
                 : "=r"(r0), "=r"(r1), "=r"(r2), "=r"(r3) : "r"(addr));
}

DI void mma16816(float* c, const unsigned* a, unsigned b0, unsigned b1) {
    asm volatile(
        "mma.sync.aligned.m16n8k16.row.col.f32.f16.f16.f32 "
        "{%0,%1,%2,%3}, {%4,%5,%6,%7}, {%8,%9}, {%0,%1,%2,%3};"
        : "+f"(c[0]), "+f"(c[1]), "+f"(c[2]), "+f"(c[3])
        : "r"(a[0]), "r"(a[1]), "r"(a[2]), "r"(a[3]), "r"(b0), "r"(b1));
}

// ---------------------------------------------------------------------------
// Prep kernels
// ---------------------------------------------------------------------------
__global__ void conv_x_kernel(const float* __restrict__ in, __half* __restrict__ o) {
    int i = blockIdx.x * blockDim.x + threadIdx.x;  // over (BB*FF)/2
    float2 v = reinterpret_cast<const float2*>(in)[i];
    reinterpret_cast<__half2*>(o)[i] = __floats2half2_rn(v.x, v.y);
}

// in: slices [s][R rows][Cin cols] f32 -> out: [s][Npad rows][R cols] fp16 (transpose+pad)
__global__ void transpose_conv(const float* __restrict__ in, __half* __restrict__ out,
                               int R, int Cin, int Npad) {
    __shared__ float t[32][33];
    long long s = blockIdx.z;
    const float* ip = in + s * (long long)R * Cin;
    __half* op = out + s * (long long)Npad * R;
    int r0 = blockIdx.x << 5, c0 = blockIdx.y << 5;
    int tx = threadIdx.x;
#pragma unroll
    for (int dy = threadIdx.y; dy < 32; dy += 8) {
        int cc = c0 + tx;
        t[dy][tx] = (cc < Cin) ? ip[(long long)(r0 + dy) * Cin + cc] : 0.f;
    }
    __syncthreads();
#pragma unroll
    for (int dy = threadIdx.y; dy < 32; dy += 8) {
        op[(long long)(c0 + dy) * R + r0 + tx] = __float2half_rn(t[tx][dy]);
    }
}

__global__ void pad_bout_kernel(const float* __restrict__ b, float* __restrict__ o) {
    int i = blockIdx.x * blockDim.x + threadIdx.x;
    if (i < KK * CPAD) {
        int k = i >> 7, c = i & 127;
        o[i] = (c < CC) ? b[k * CC + c] : 0.f;
    }
}

__global__ void reduce_mean_kernel(const float* __restrict__ lg, float* __restrict__ out) {
    int i = blockIdx.x * blockDim.x + threadIdx.x;
    if (i >= BB * CC) return;
    int b = i / CC, c = i - b * CC;
    float s = 0.f;
#pragma unroll
    for (int k = 0; k < KK; k++) s += lg[((long long)k * BB + b) * CPAD + c];
    out[i] = s * (1.0f / KK);
}

// ---------------------------------------------------------------------------
// HMMA GEMM:  D[128, BN] = A[128, Kd] @ Wt[BN, Kd]^T  (+bias, relu)
// A row-major (K-major), Wt row-major [n][k] (K-major). Kd % 64 == 0.
// grid: (Ntot/BN, BB/128, KK), 256 threads (8 warps, 2(M) x 4(N) warp grid).
// ---------------------------------------------------------------------------
template <int BN, bool RELU, bool OUT_F16>
__global__ void __launch_bounds__(256) gemm_ens(
    const __half* __restrict__ A, long long sAk, int Kdim,
    const __half* __restrict__ Wt, long long sWk,
    const float* __restrict__ bias, long long sBk,
    void* __restrict__ Out, long long sOk, int ldo) {
    extern __shared__ __align__(1024) char smem_raw[];
    unsigned sb0 = smem_u32(smem_raw);
    const unsigned sb = (sb0 + 1023u) & ~1023u;  // 1024-align: keeps swizzle analysis exact

    constexpr int WN = BN / 4;       // warp tile N (64 or 32)
    constexpr int NT = WN / 16;      // 16-wide B ldmatrix tiles per warp (4 or 2)
    constexpr int N8 = WN / 8;       // n8 mma tiles per warp (8 or 4)
    constexpr int MT = 4;            // 64 / 16 m-tiles per warp
    constexpr int ATILE = 128 * 128;       // bytes per A stage (128 rows x 64 fp16)
    constexpr int BTILE = BN * 128;        // bytes per B stage
    constexpr int STAGE = ATILE + BTILE;
    constexpr int STAGES = 3;

    const int tid = threadIdx.x;
    const int lane = tid & 31;
    const int wid = tid >> 5;
    const int warp_m = wid & 1;      // 0..1
    const int warp_n = wid >> 1;     // 0..3

    const __half* Ak =
        A + (long long)blockIdx.z * sAk + (long long)blockIdx.y * 128 * Kdim;
    const __half* Bk =
        Wt + (long long)blockIdx.z * sWk + (long long)blockIdx.x * BN * Kdim;

    const int NTK = Kdim >> 6;  // K chunks of 64 fp16

    auto load_stage = [&](int s, int kt) {
        const unsigned offA = sb + s * STAGE;
        const unsigned offB = offA + ATILE;
        const int ko = kt << 6;
#pragma unroll
        for (int i = 0; i < 4; i++) {  // A: 1024 x 16B granules
            int c = tid + i * 256;
            int r = c >> 3, q = c & 7;
            cpa16(offA + swz((unsigned)(r * 128 + q * 16)),
                  Ak + (long long)r * Kdim + ko + q * 8);
        }
#pragma unroll
        for (int i = 0; i < BN / 32; i++) {  // B: BN*8 x 16B granules
            int c = tid + i * 256;
            int r = c >> 3, q = c & 7;
            cpa16(offB + swz((unsigned)(r * 128 + q * 16)),
                  Bk + (long long)r * Kdim + ko + q * 8);
        }
        cpa_commit();
    };

    // per-thread ldmatrix base offsets (relative to tile base, pre-swizzle)
    const int lrow = lane & 15;                         // row within 16 (m or n)
    const unsigned lkb = (unsigned)((lane >> 4) * 16);  // k-half granule (bytes)
    const unsigned aBase = (unsigned)((warp_m * 64 + lrow) * 128) + lkb;
    const unsigned bBase = (unsigned)((warp_n * WN + lrow) * 128) + lkb;

    float acc[MT][N8][4];
#pragma unroll
    for (int mt = 0; mt < MT; mt++)
#pragma unroll
        for (int j = 0; j < N8; j++)
#pragma unroll
            for (int e = 0; e < 4; e++) acc[mt][j][e] = 0.f;

    // prologue: stages 0,1
    load_stage(0, 0);
    load_stage(1, 1);

    for (int kt = 0; kt < NTK; ++kt) {
        __syncthreads();  // all warps done with the slot we are about to refill
        if (kt + 2 < NTK) load_stage((kt + 2) % STAGES, kt + 2);
        if (kt + 2 < NTK)      cpa_wait<2>();
        else if (kt + 1 < NTK) cpa_wait<1>();
        else                   cpa_wait<0>();
        __syncthreads();  // stage kt visible to all warps

        const unsigned sA = sb + (kt % STAGES) * STAGE;
        const unsigned sB = sA + ATILE;
#pragma unroll
        for (int k16 = 0; k16 < 4; k16++) {
            unsigned a[MT][4];
#pragma unroll
            for (int mt = 0; mt < MT; mt++)
                ldsm4(a[mt][0], a[mt][1], a[mt][2], a[mt][3],
                      sA + swz(aBase + (unsigned)(mt * 2048 + k16 * 32)));
#pragma unroll
            for (int nt = 0; nt < NT; nt++) {
                unsigned b0, b1, b2, b3;
                ldsm4(b0, b1, b2, b3,
                      sB + swz(bBase + (unsigned)(nt * 2048 + k16 * 32)));
#pragma unroll
                for (int mt = 0; mt < MT; mt++) {
                    mma16816(acc[mt][2 * nt],     a[mt], b0, b2);
                    mma16816(acc[mt][2 * nt + 1], a[mt], b1, b3);
                }
            }
        }
    }

    // ---- epilogue: bias + (relu) + store ----
    const int r = lane >> 2;          // 0..7
    const int cq = (lane & 3) * 2;    // 0,2,4,6
    const float* bp = bias + (long long)blockIdx.z * sBk + (long long)blockIdx.x * BN +
                      warp_n * WN + cq;
    float2 bv[N8];
#pragma unroll
    for (int j = 0; j < N8; j++) bv[j] = *reinterpret_cast<const float2*>(bp + j * 8);

    const long long obase =
        (long long)blockIdx.z * sOk +
        ((long long)blockIdx.y * 128 + warp_m * 64 + r) * (long long)ldo +
        (long long)blockIdx.x * BN + warp_n * WN + cq;

#pragma unroll
    for (int mt = 0; mt < MT; mt++) {
        const long long ro0 = obase + (long long)(mt * 16) * ldo;
        const long long ro1 = ro0 + 8LL * ldo;
#pragma unroll
        for (int j = 0; j < N8; j++) {
            float v00 = acc[mt][j][0] + bv[j].x;
            float v01 = acc[mt][j][1] + bv[j].y;
            float v10 = acc[mt][j][2] + bv[j].x;
            float v11 = acc[mt][j][3] + bv[j].y;
            if (RELU) {
                v00 = fmaxf(v00, 0.f); v01 = fmaxf(v01, 0.f);
                v10 = fmaxf(v10, 0.f); v11 = fmaxf(v11, 0.f);
            }
            if (OUT_F16) {
                __half* ob = reinterpret_cast<__half*>(Out);
                *reinterpret_cast<__half2*>(ob + ro0 + j * 8) = __floats2half2_rn(v00, v01);
                *reinterpret_cast<__half2*>(ob + ro1 + j * 8) = __floats2half2_rn(v10, v11);
            } else {
                float* of = reinterpret_cast<float*>(Out);
                *reinterpret_cast<float2*>(of + ro0 + j * 8) = make_float2(v00, v01);
                *reinterpret_cast<float2*>(of + ro1 + j * 8) = make_float2(v10, v11);
            }
        }
    }
}

// ---------------------------------------------------------------------------
// Launch
// ---------------------------------------------------------------------------
extern "C" void kernel_launch(void* const* d_in, const int* in_sizes, int n_in,
                              void* d_out, int out_size) {
    (void)in_sizes; (void)n_in; (void)out_size;
    const float* x     = (const float*)d_in[0];
    const float* W_in  = (const float*)d_in[1];
    const float* b_in  = (const float*)d_in[2];
    const float* W_hid = (const float*)d_in[3];
    const float* b_hid = (const float*)d_in[4];
    const float* W_out = (const float*)d_in[5];
    const float* b_out = (const float*)d_in[6];
    float* out = (float*)d_out;

    __half *xb, *wtin, *wthid, *wtout, *a0, *a1;
    float *bpad, *lg;
    cudaGetSymbolAddress((void**)&xb, g_xb);
    cudaGetSymbolAddress((void**)&wtin, g_wt_in);
    cudaGetSymbolAddress((void**)&wthid, g_wt_hid);
    cudaGetSymbolAddress((void**)&wtout, g_wt_out);
    cudaGetSymbolAddress((void**)&bpad, g_bout_pad);
    cudaGetSymbolAddress((void**)&a0, g_act0);
    cudaGetSymbolAddress((void**)&a1, g_act1);
    cudaGetSymbolAddress((void**)&lg, g_logits);

    constexpr int SMEM256 = 1024 + 3 * (128 * 128 + 256 * 128);  // 148480
    constexpr int SMEM128 = 1024 + 3 * (128 * 128 + 128 * 128);  // 99328
    cudaFuncSetAttribute(gemm_ens<256, true, true>,
                         cudaFuncAttributeMaxDynamicSharedMemorySize, SMEM256);
    cudaFuncSetAttribute(gemm_ens<128, false, false>,
                         cudaFuncAttributeMaxDynamicSharedMemorySize, SMEM128);

    // ---- prep: convert x, transpose weights to K-major fp16 ----
    conv_x_kernel<<<(BB * FF / 2) / 256, 256>>>(x, xb);
    transpose_conv<<<dim3(FF / 32, HH / 32, KK), dim3(32, 8)>>>(W_in, wtin, FF, HH, HH);
    transpose_conv<<<dim3(HH / 32, HH / 32, NL * KK), dim3(32, 8)>>>(W_hid, wthid, HH, HH, HH);
    transpose_conv<<<dim3(HH / 32, CPAD / 32, KK), dim3(32, 8)>>>(W_out, wtout, HH, CC, CPAD);
    pad_bout_kernel<<<(KK * CPAD + 255) / 256, 256>>>(b_out, bpad);

    // ---- L0: [4096,512] x [512,1024] per k -> act0 (relu, fp16) ----
    gemm_ens<256, true, true><<<dim3(HH / 256, BB / 128, KK), 256, SMEM256>>>(
        xb, 0LL, FF,
        wtin, (long long)HH * FF,
        b_in, (long long)HH,
        a0, (long long)BB * HH, HH);

    // ---- L1..L3: hidden layers, ping-pong act0/act1 ----
    for (int i = 0; i < NL; i++) {
        __half* src = (i & 1) ? a1 : a0;
        __half* dst = (i & 1) ? a0 : a1;
        gemm_ens<256, true, true><<<dim3(HH / 256, BB / 128, KK), 256, SMEM256>>>(
            src, (long long)BB * HH, HH,
            wthid + (long long)i * KK * HH * HH, (long long)HH * HH,
            b_hid + (long long)i * KK * HH, (long long)HH,
            dst, (long long)BB * HH, HH);
    }
    // after i=0: a0->a1; i=1: a1->a0; i=2: a0->a1  => final act in a1

    // ---- L4: [4096,1024] x [1024,128pad] per k -> f32 logits (no relu) ----
    gemm_ens<128, false, false><<<dim3(1, BB / 128, KK), 256, SMEM128>>>(
        a1, (long long)BB * HH, HH,
        wtout, (long long)CPAD * HH,
        bpad, (long long)CPAD,
        lg, (long long)BB * CPAD, CPAD);

    // ---- mean over ensemble ----
    reduce_mean_kernel<<<(BB * CC + 255) / 256, 256>>>(lg, out);
}

// round 14
// speedup vs baseline: 1.0010x; 1.0010x over previous
#include <cuda_runtime.h>
#include <cuda_fp16.h>

// ---------------------------------------------------------------------------
// TabM packed ensemble: out = mean_k( MLP_k(x) ), K=32 MLPs 512->1024^4->100.
// Plain sm_103 target (no 'a'): tcgen05 unavailable -> mma.sync.m16n8k16 fp16
// (fp32 accum), cp.async 3-stage smem pipeline, register double-buffered
// ldmatrix fragments, cp.async issue interleaved into the k16 loop.
// ---------------------------------------------------------------------------

#define DI static __device__ __forceinline__

constexpr int BB = 4096;   // batch
constexpr int FF = 512;    // in features
constexpr int HH = 1024;   // hidden
constexpr int CC = 100;    // classes
constexpr int KK = 32;     // ensemble
constexpr int NL = 3;      // hidden->hidden layers
constexpr int CPAD = 128;  // padded classes

// ---- device scratch (__device__ globals: the sanctioned no-alloc path) ----
__device__ __half g_xb[BB * FF];                // x in fp16
__device__ __half g_wt_in[KK * HH * FF];        // W_in^T  [k][h][f]  (K-major)
__device__ __half g_wt_hid[NL * KK * HH * HH];  // W_hid^T [i][k][j][h]
__device__ __half g_wt_out[KK * CPAD * HH];     // W_out^T [k][c_pad][h], zero-padded
__device__ float  g_bout_pad[KK * CPAD];
__device__ __half g_act0[KK * BB * HH];
__device__ __half g_act1[KK * BB * HH];
__device__ float  g_logits[KK * BB * CPAD];     // per-k fp32 logits (padded)

// ---------------------------------------------------------------------------
// PTX helpers (sm_80+ baseline ISA only)
// ---------------------------------------------------------------------------
DI unsigned smem_u32(const void* p) { return (unsigned)__cvta_generic_to_shared(p); }

DI void cpa16(unsigned dst, const void* src) {
    asm volatile("cp.async.cg.shared.global [%0], [%1], 16;"
                 ::"r"(dst), "l"(__cvta_generic_to_global(src)) : "memory");
}
DI void cpa_commit() { asm volatile("cp.async.commit_group;" ::: "memory"); }
template <int N>
DI void cpa_wait() { asm volatile("cp.async.wait_group %0;" ::"n"(N) : "memory"); }

DI unsigned swz(unsigned off) { return off ^ ((off >> 3) & 0x70); }  // SW128 / Swizzle<3,4,3>

DI void ldsm4(unsigned& r0, unsigned& r1, unsigned& r2, unsigned& r3, unsigned addr) {
    asm volatile("ldmatrix.sync.aligned.m8n8.x4.shared.b16 {%0,%1,%2,%3}, [%4];"
                 : "=r"(r0), "=r"(r1), "=r"(r2), "=r"(r3) : "r"(addr));
}

DI void mma16816(float* c, const unsigned* a, unsigned b0, unsigned b1) {
    asm volatile(
        "mma.sync.aligned.m16n8k16.row.col.f32.f16.f16.f32 "
        "{%0,%1,%2,%3}, {%4,%5,%6,%7}, {%8,%9}, {%0,%1,%2,%3};"
        : "+f"(c[0]), "+f"(c[1]), "+f"(c[2]), "+f"(c[3])
        : "r"(a[0]), "r"(a[1]), "r"(a[2]), "r"(a[3]), "r"(b0), "r"(b1));
}

// ---------------------------------------------------------------------------
// Prep kernels (fused into 2 launches so ncu -s 5 lands on a hidden GEMM)
// ---------------------------------------------------------------------------
// prep_misc: x f32->f16 (as half2 over BB*FF/2) and b_out padding (KK*CPAD).
__global__ void prep_misc(const float* __restrict__ x, __half* __restrict__ xb,
                          const float* __restrict__ bo, float* __restrict__ bpad) {
    constexpr int N1 = BB * FF / 2;
    int i = blockIdx.x * blockDim.x + threadIdx.x;
    if (i < N1) {
        float2 v = reinterpret_cast<const float2*>(x)[i];
        reinterpret_cast<__half2*>(xb)[i] = __floats2half2_rn(v.x, v.y);
    } else {
        int j = i - N1;
        if (j < KK * CPAD) {
            int k = j >> 7, c = j & 127;
            bpad[j] = (c < CC) ? bo[k * CC + c] : 0.f;
        }
    }
}

// transpose_all: all weight transposes in ONE launch.
// grid (32, 32, 160): z<32 -> W_in[k] (R=512,Cin=1024,Npad=1024);
// z in [32,128) -> W_hid (R=1024,Cin=1024,Npad=1024); z>=128 -> W_out (R=1024,Cin=100,Npad=128).
__global__ void transpose_all(const float* __restrict__ W_in, __half* __restrict__ wtin,
                              const float* __restrict__ W_hid, __half* __restrict__ wthid,
                              const float* __restrict__ W_out, __half* __restrict__ wtout) {
    __shared__ float t[32][33];
    int z = blockIdx.z;
    const float* ip; __half* op; int R, Cin, Npad;
    if (z < 32) {
        R = FF; Cin = HH; Npad = HH;
        ip = W_in + (long long)z * FF * HH;
        op = wtin + (long long)z * HH * FF;
    } else if (z < 128) {
        R = HH; Cin = HH; Npad = HH;
        ip = W_hid + (long long)(z - 32) * HH * HH;
        op = wthid + (long long)(z - 32) * HH * HH;
    } else {
        R = HH; Cin = CC; Npad = CPAD;
        ip = W_out + (long long)(z - 128) * HH * CC;
        op = wtout + (long long)(z - 128) * CPAD * HH;
    }
    int r0 = blockIdx.x << 5, c0 = blockIdx.y << 5;
    if (r0 >= R || c0 >= Npad) return;
    int tx = threadIdx.x;
#pragma unroll
    for (int dy = threadIdx.y; dy < 32; dy += 8) {
        int cc = c0 + tx;
        t[dy][tx] = (cc < Cin) ? ip[(long long)(r0 + dy) * Cin + cc] : 0.f;
    }
    __syncthreads();
#pragma unroll
    for (int dy = threadIdx.y; dy < 32; dy += 8) {
        op[(long long)(c0 + dy) * R + r0 + tx] = __float2half_rn(t[tx][dy]);
    }
}

__global__ void reduce_mean_kernel(const float* __restrict__ lg, float* __restrict__ out) {
    int i = blockIdx.x * blockDim.x + threadIdx.x;
    if (i >= BB * CC) return;
    int b = i / CC, c = i - b * CC;
    float s = 0.f;
#pragma unroll
    for (int k = 0; k < KK; k++) s += lg[((long long)k * BB + b) * CPAD + c];
    out[i] = s * (1.0f / KK);
}

// ---------------------------------------------------------------------------
// HMMA GEMM:  D[128, BN] = A[128, Kd] @ Wt[BN, Kd]^T  (+bias, relu)
// A row-major (K-major), Wt row-major [n][k] (K-major). Kd % 64 == 0.
// grid: (Ntot/BN, BB/128, KK), 256 threads (8 warps, 2(M) x 4(N) warp grid).
// ---------------------------------------------------------------------------
template <int BN, bool RELU, bool OUT_F16>
__global__ void __launch_bounds__(256) gemm_ens(
    const __half* __restrict__ A, long long sAk, int Kdim,
    const __half* __restrict__ Wt, long long sWk,
    const float* __restrict__ bias, long long sBk,
    void* __restrict__ Out, long long sOk, int ldo) {
    extern __shared__ __align__(1024) char smem_raw[];
    unsigned sb0 = smem_u32(smem_raw);
    const unsigned sb = (sb0 + 1023u) & ~1023u;  // 1024-align keeps swizzle analysis exact

    constexpr int WN = BN / 4;        // warp tile N (64 or 32)
    constexpr int NT = WN / 16;       // 16-row B ldmatrix tiles per warp (4 or 2)
    constexpr int N8 = WN / 8;        // n8 mma tiles per warp (8 or 4)
    constexpr int MT = 4;             // 64/16 m-tiles per warp
    constexpr int ATILE = 128 * 128;  // bytes per A stage
    constexpr int BTILE = BN * 128;   // bytes per B stage
    constexpr int STAGE = ATILE + BTILE;
    constexpr int STAGES = 3;
    constexpr int NBH = BN / 64;      // B cp.async granule-groups per half

    const int tid = threadIdx.x;
    const int lane = tid & 31;
    const int wid = tid >> 5;
    const int warp_m = wid & 1;   // 0..1
    const int warp_n = wid >> 1;  // 0..3

    const __half* Ak =
        A + (long long)blockIdx.z * sAk + (long long)blockIdx.y * 128 * Kdim;
    const __half* Bk =
        Wt + (long long)blockIdx.z * sWk + (long long)blockIdx.x * BN * Kdim;

    const int NTK = Kdim >> 6;  // K chunks of 64 fp16

    auto load_A_chunk = [&](int s, int kt) {
        const unsigned offA = sb + s * STAGE;
        const int ko = kt << 6;
#pragma unroll
        for (int i = 0; i < 4; i++) {
            int c = tid + i * 256;
            int r = c >> 3, q = c & 7;
            cpa16(offA + swz((unsigned)(r * 128 + q * 16)),
                  Ak + (long long)r * Kdim + ko + q * 8);
        }
    };
    auto load_B_half = [&](int s, int kt, int half) {
        const unsigned offB = sb + s * STAGE + ATILE;
        const int ko = kt << 6;
#pragma unroll
        for (int i = 0; i < NBH; i++) {
            int c = tid + (half * NBH + i) * 256;
            int r = c >> 3, q = c & 7;
            cpa16(offB + swz((unsigned)(r * 128 + q * 16)),
                  Bk + (long long)r * Kdim + ko + q * 8);
        }
    };

    // per-thread ldmatrix base offsets (relative to tile base, pre-swizzle)
    const int lrow = lane & 15;                         // row within 16 (m or n)
    const unsigned lkb = (unsigned)((lane >> 4) * 16);  // k-half granule (bytes)
    const unsigned aBase = (unsigned)((warp_m * 64 + lrow) * 128) + lkb;
    const unsigned bBase = (unsigned)((warp_n * WN + lrow) * 128) + lkb;

    unsigned afr[2][MT][4], bfr[2][NT][4];
    float acc[MT][N8][4];
#pragma unroll
    for (int mt = 0; mt < MT; mt++)
#pragma unroll
        for (int j = 0; j < N8; j++)
#pragma unroll
            for (int e = 0; e < 4; e++) acc[mt][j][e] = 0.f;

    // prologue: fill stages 0, 1
    load_A_chunk(0, 0); load_B_half(0, 0, 0); load_B_half(0, 0, 1); cpa_commit();
    load_A_chunk(1, 1); load_B_half(1, 1, 0); load_B_half(1, 1, 1); cpa_commit();

    for (int kt = 0; kt < NTK; ++kt) {
        if (kt + 1 < NTK) cpa_wait<1>(); else cpa_wait<0>();
        __syncthreads();  // stage kt visible to all warps; all warps done with kt-1

        const unsigned sA = sb + (kt % STAGES) * STAGE;
        const unsigned sB = sA + ATILE;
        const bool pf = (kt + 2 < NTK);
        const int ps = (kt + 2) % STAGES;

        // fragment prologue: k16 = 0 into buffer 0
#pragma unroll
        for (int mt = 0; mt < MT; mt++)
            ldsm4(afr[0][mt][0], afr[0][mt][1], afr[0][mt][2], afr[0][mt][3],
                  sA + swz(aBase + (unsigned)(mt * 2048)));
#pragma unroll
        for (int nt = 0; nt < NT; nt++)
            ldsm4(bfr[0][nt][0], bfr[0][nt][1], bfr[0][nt][2], bfr[0][nt][3],
                  sB + swz(bBase + (unsigned)(nt * 2048)));

#pragma unroll
        for (int k16 = 0; k16 < 4; k16++) {
            const int cur = k16 & 1, nxt = cur ^ 1;
            // prefetch next k16 fragments (register double buffer)
            if (k16 < 3) {
#pragma unroll
                for (int mt = 0; mt < MT; mt++)
                    ldsm4(afr[nxt][mt][0], afr[nxt][mt][1], afr[nxt][mt][2], afr[nxt][mt][3],
                          sA + swz(aBase + (unsigned)(mt * 2048 + (k16 + 1) * 32)));
#pragma unroll
                for (int nt = 0; nt < NT; nt++)
                    ldsm4(bfr[nxt][nt][0], bfr[nxt][nt][1], bfr[nxt][nt][2], bfr[nxt][nt][3],
                          sB + swz(bBase + (unsigned)(nt * 2048 + (k16 + 1) * 32)));
            }
            // spread the cp.async issue of stage kt+2 across k16 steps
            if (pf) {
                if (k16 == 0) load_A_chunk(ps, kt + 2);
                else if (k16 == 1) load_B_half(ps, kt + 2, 0);
                else if (k16 == 2) load_B_half(ps, kt + 2, 1);
                else cpa_commit();
            }
            // 32 (or 16) MMAs on current buffer — hides the ldsm latency above
#pragma unroll
            for (int nt = 0; nt < NT; nt++) {
#pragma unroll
                for (int mt = 0; mt < MT; mt++) {
                    mma16816(acc[mt][2 * nt],     afr[cur][mt], bfr[cur][nt][0], bfr[cur][nt][2]);
                    mma16816(acc[mt][2 * nt + 1], afr[cur][mt], bfr[cur][nt][1], bfr[cur][nt][3]);
                }
            }
        }
    }

    // ---- epilogue: bias + (relu) + store ----
    const int r = lane >> 2;        // 0..7
    const int cq = (lane & 3) * 2;  // 0,2,4,6
    const float* bp = bias + (long long)blockIdx.z * sBk + (long long)blockIdx.x * BN +
                      warp_n * WN + cq;
    float2 bv[N8];
#pragma unroll
    for (int j = 0; j < N8; j++) bv[j] = *reinterpret_cast<const float2*>(bp + j * 8);

    const long long obase =
        (long long)blockIdx.z * sOk +
        ((long long)blockIdx.y * 128 + warp_m * 64 + r) * (long long)ldo +
        (long long)blockIdx.x * BN + warp_n * WN + cq;

#pragma unroll
    for (int mt = 0; mt < MT; mt++) {
        const long long ro0 = obase + (long long)(mt * 16) * ldo;
        const long long ro1 = ro0 + 8LL * ldo;
#pragma unroll
        for (int j = 0; j < N8; j++) {
            float v00 = acc[mt][j][0] + bv[j].x;
            float v01 = acc[mt][j][1] + bv[j].y;
            float v10 = acc[mt][j][2] + bv[j].x;
            float v11 = acc[mt][j][3] + bv[j].y;
            if (RELU) {
                v00 = fmaxf(v00, 0.f); v01 = fmaxf(v01, 0.f);
                v10 = fmaxf(v10, 0.f); v11 = fmaxf(v11, 0.f);
            }
            if (OUT_F16) {
                __half* ob = reinterpret_cast<__half*>(Out);
                *reinterpret_cast<__half2*>(ob + ro0 + j * 8) = __floats2half2_rn(v00, v01);
                *reinterpret_cast<__half2*>(ob + ro1 + j * 8) = __floats2half2_rn(v10, v11);
            } else {
                float* of = reinterpret_cast<float*>(Out);
                *reinterpret_cast<float2*>(of + ro0 + j * 8) = make_float2(v00, v01);
                *reinterpret_cast<float2*>(of + ro1 + j * 8) = make_float2(v10, v11);
            }
        }
    }
}

// ---------------------------------------------------------------------------
// Launch
// ---------------------------------------------------------------------------
extern "C" void kernel_launch(void* const* d_in, const int* in_sizes, int n_in,
                              void* d_out, int out_size) {
    (void)in_sizes; (void)n_in; (void)out_size;
    const float* x     = (const float*)d_in[0];
    const float* W_in  = (const float*)d_in[1];
    const float* b_in  = (const float*)d_in[2];
    const float* W_hid = (const float*)d_in[3];
    const float* b_hid = (const float*)d_in[4];
    const float* W_out = (const float*)d_in[5];
    const float* b_out = (const float*)d_in[6];
    float* out = (float*)d_out;

    __half *xb, *wtin, *wthid, *wtout, *a0, *a1;
    float *bpad, *lg;
    cudaGetSymbolAddress((void**)&xb, g_xb);
    cudaGetSymbolAddress((void**)&wtin, g_wt_in);
    cudaGetSymbolAddress((void**)&wthid, g_wt_hid);
    cudaGetSymbolAddress((void**)&wtout, g_wt_out);
    cudaGetSymbolAddress((void**)&bpad, g_bout_pad);
    cudaGetSymbolAddress((void**)&a0, g_act0);
    cudaGetSymbolAddress((void**)&a1, g_act1);
    cudaGetSymbolAddress((void**)&lg, g_logits);

    constexpr int SMEM256 = 1024 + 3 * (128 * 128 + 256 * 128);  // 148480
    constexpr int SMEM128 = 1024 + 3 * (128 * 128 + 128 * 128);  // 99328
    cudaFuncSetAttribute(gemm_ens<256, true, true>,
                         cudaFuncAttributeMaxDynamicSharedMemorySize, SMEM256);
    cudaFuncSetAttribute(gemm_ens<128, false, false>,
                         cudaFuncAttributeMaxDynamicSharedMemorySize, SMEM128);

    // ---- prep (2 launches) ----
    constexpr int NPREP = BB * FF / 2 + KK * CPAD;
    prep_misc<<<(NPREP + 255) / 256, 256>>>(x, xb, b_out, bpad);
    transpose_all<<<dim3(32, 32, 160), dim3(32, 8)>>>(W_in, wtin, W_hid, wthid, W_out, wtout);

    // ---- L0: [4096,512] x [512,1024] per k -> act0 (relu, fp16) ----
    gemm_ens<256, true, true><<<dim3(HH / 256, BB / 128, KK), 256, SMEM256>>>(
        xb, 0LL, FF,
        wtin, (long long)HH * FF,
        b_in, (long long)HH,
        a0, (long long)BB * HH, HH);

    // ---- L1..L3: hidden layers, ping-pong act0/act1 ----
    for (int i = 0; i < NL; i++) {
        __half* src = (i & 1) ? a1 : a0;
        __half* dst = (i & 1) ? a0 : a1;
        gemm_ens<256, true, true><<<dim3(HH / 256, BB / 128, KK), 256, SMEM256>>>(
            src, (long long)BB * HH, HH,
            wthid + (long long)i * KK * HH * HH, (long long)HH * HH,
            b_hid + (long long)i * KK * HH, (long long)HH,
            dst, (long long)BB * HH, HH);
    }
    // after i=0: a0->a1; i=1: a1->a0; i=2: a0->a1  => final act in a1

    // ---- L4: [4096,1024] x [1024,128pad] per k -> f32 logits (no relu) ----
    gemm_ens<128, false, false><<<dim3(1, BB / 128, KK), 256, SMEM128>>>(
        a1, (long long)BB * HH, HH,
        wtout, (long long)CPAD * HH,
        bpad, (long long)CPAD,
        lg, (long long)BB * CPAD, CPAD);

    // ---- mean over ensemble ----
    reduce_mean_kernel<<<(BB * CC + 255) / 256, 256>>>(lg, out);
}

// round 15
// speedup vs baseline: 1.0249x; 1.0239x over previous
#include <cuda_runtime.h>
#include <cuda_fp16.h>

// ---------------------------------------------------------------------------
// TabM packed ensemble: out = mean_k( MLP_k(x) ), K=32 MLPs 512->1024^4->100.
// Plain sm_103 target: mma.sync.m16n8k16 fp16 (fp32 accum), cp.async 3-stage
// pipeline. R15: 16 warps x (32x64) warp tiles (occ 12.4%->25%) instead of
// 8 x (64x64); single-buffered fragments to fit the 128-reg cap @512 thr.
// ---------------------------------------------------------------------------

#define DI static __device__ __forceinline__

constexpr int BB = 4096;   // batch
constexpr int FF = 512;    // in features
constexpr int HH = 1024;   // hidden
constexpr int CC = 100;    // classes
constexpr int KK = 32;     // ensemble
constexpr int NL = 3;      // hidden->hidden layers
constexpr int CPAD = 128;  // padded classes

// ---- device scratch (__device__ globals: the sanctioned no-alloc path) ----
__device__ __half g_xb[BB * FF];                // x in fp16
__device__ __half g_wt_in[KK * HH * FF];        // W_in^T  [k][h][f]  (K-major)
__device__ __half g_wt_hid[NL * KK * HH * HH];  // W_hid^T [i][k][j][h]
__device__ __half g_wt_out[KK * CPAD * HH];     // W_out^T [k][c_pad][h], zero-padded
__device__ float  g_bout_pad[KK * CPAD];
__device__ __half g_act0[KK * BB * HH];
__device__ __half g_act1[KK * BB * HH];
__device__ float  g_logits[KK * BB * CPAD];     // per-k fp32 logits (padded)

// ---------------------------------------------------------------------------
// PTX helpers (sm_80+ baseline ISA only)
// ---------------------------------------------------------------------------
DI unsigned smem_u32(const void* p) { return (unsigned)__cvta_generic_to_shared(p); }

DI void cpa16(unsigned dst, const void* src) {
    asm volatile("cp.async.cg.shared.global [%0], [%1], 16;"
                 ::"r"(dst), "l"(__cvta_generic_to_global(src)) : "memory");
}
DI void cpa_commit() { asm volatile("cp.async.commit_group;" ::: "memory"); }
template <int N>
DI void cpa_wait() { asm volatile("cp.async.wait_group %0;" ::"n"(N) : "memory"); }

DI unsigned swz(unsigned off) { return off ^ ((off >> 3) & 0x70); }  // SW128 / Swizzle<3,4,3>

DI void ldsm4(unsigned& r0, unsigned& r1, unsigned& r2, unsigned& r3, unsigned addr) {
    asm volatile("ldmatrix.sync.aligned.m8n8.x4.shared.b16 {%0,%1,%2,%3}, [%4];"
                 : "=r"(r0), "=r"(r1), "=r"(r2), "=r"(r3) : "r"(addr));
}

DI void mma16816(float* c, const unsigned* a, unsigned b0, unsigned b1) {
    asm volatile(
        "mma.sync.aligned.m16n8k16.row.col.f32.f16.f16.f32 "
        "{%0,%1,%2,%3}, {%4,%5,%6,%7}, {%8,%9}, {%0,%1,%2,%3};"
        : "+f"(c[0]), "+f"(c[1]), "+f"(c[2]), "+f"(c[3])
        : "r"(a[0]), "r"(a[1]), "r"(a[2]), "r"(a[3]), "r"(b0), "r"(b1));
}

// ---------------------------------------------------------------------------
// Prep kernels (2 launches)
// ---------------------------------------------------------------------------
__global__ void prep_misc(const float* __restrict__ x, __half* __restrict__ xb,
                          const float* __restrict__ bo, float* __restrict__ bpad) {
    constexpr int N1 = BB * FF / 2;
    int i = blockIdx.x * blockDim.x + threadIdx.x;
    if (i < N1) {
        float2 v = reinterpret_cast<const float2*>(x)[i];
        reinterpret_cast<__half2*>(xb)[i] = __floats2half2_rn(v.x, v.y);
    } else {
        int j = i - N1;
        if (j < KK * CPAD) {
            int k = j >> 7, c = j & 127;
            bpad[j] = (c < CC) ? bo[k * CC + c] : 0.f;
        }
    }
}

// transpose_all: all weight transposes in ONE launch (see R14 comment).
__global__ void transpose_all(const float* __restrict__ W_in, __half* __restrict__ wtin,
                              const float* __restrict__ W_hid, __half* __restrict__ wthid,
                              const float* __restrict__ W_out, __half* __restrict__ wtout) {
    __shared__ float t[32][33];
    int z = blockIdx.z;
    const float* ip; __half* op; int R, Cin, Npad;
    if (z < 32) {
        R = FF; Cin = HH; Npad = HH;
        ip = W_in + (long long)z * FF * HH;
        op = wtin + (long long)z * HH * FF;
    } else if (z < 128) {
        R = HH; Cin = HH; Npad = HH;
        ip = W_hid + (long long)(z - 32) * HH * HH;
        op = wthid + (long long)(z - 32) * HH * HH;
    } else {
        R = HH; Cin = CC; Npad = CPAD;
        ip = W_out + (long long)(z - 128) * HH * CC;
        op = wtout + (long long)(z - 128) * CPAD * HH;
    }
    int r0 = blockIdx.x << 5, c0 = blockIdx.y << 5;
    if (r0 >= R || c0 >= Npad) return;
    int tx = threadIdx.x;
#pragma unroll
    for (int dy = threadIdx.y; dy < 32; dy += 8) {
        int cc = c0 + tx;
        t[dy][tx] = (cc < Cin) ? ip[(long long)(r0 + dy) * Cin + cc] : 0.f;
    }
    __syncthreads();
#pragma unroll
    for (int dy = threadIdx.y; dy < 32; dy += 8) {
        op[(long long)(c0 + dy) * R + r0 + tx] = __float2half_rn(t[tx][dy]);
    }
}

__global__ void reduce_mean_kernel(const float* __restrict__ lg, float* __restrict__ out) {
    int i = blockIdx.x * blockDim.x + threadIdx.x;
    if (i >= BB * CC) return;
    int b = i / CC, c = i - b * CC;
    float s = 0.f;
#pragma unroll
    for (int k = 0; k < KK; k++) s += lg[((long long)k * BB + b) * CPAD + c];
    out[i] = s * (1.0f / KK);
}

// ---------------------------------------------------------------------------
// HMMA GEMM:  D[128, BN] = A[128, Kd] @ Wt[BN, Kd]^T  (+bias, relu)
// A row-major (K-major), Wt row-major [n][k] (K-major). Kd % 64 == 0.
// grid: (Ntot/BN, BB/128, KK). NWM x NWN warp grid, warp tile (128/NWM)x(BN/NWN).
// ---------------------------------------------------------------------------
template <int BN, int NWM, int NWN, bool RELU, bool OUT_F16>
__global__ void __launch_bounds__(32 * NWM * NWN) gemm_ens(
    const __half* __restrict__ A, long long sAk, int Kdim,
    const __half* __restrict__ Wt, long long sWk,
    const float* __restrict__ bias, long long sBk,
    void* __restrict__ Out, long long sOk, int ldo) {
    extern __shared__ __align__(1024) char smem_raw[];
    unsigned sb0 = smem_u32(smem_raw);
    const unsigned sb = (sb0 + 1023u) & ~1023u;  // 1024-align keeps swizzle analysis exact

    constexpr int NTH = 32 * NWM * NWN;
    constexpr int WM = 128 / NWM;     // warp tile M
    constexpr int WN = BN / NWN;      // warp tile N
    constexpr int MT = WM / 16;       // A ldmatrix tiles per warp
    constexpr int NT = WN / 16;       // B ldmatrix tiles per warp
    constexpr int N8 = WN / 8;        // n8 mma tiles per warp
    constexpr int ATILE = 128 * 128;  // bytes per A stage
    constexpr int BTILE = BN * 128;   // bytes per B stage
    constexpr int STAGE = ATILE + BTILE;
    constexpr int STAGES = 3;
    constexpr int A_IT = 1024 / NTH;      // A 16B-granule iterations
    constexpr int B_IT = (BN * 8) / NTH;  // B 16B-granule iterations
    constexpr int BH = B_IT / 2;

    const int tid = threadIdx.x;
    const int lane = tid & 31;
    const int wid = tid >> 5;
    const int warp_m = wid % NWM;
    const int warp_n = wid / NWM;

    const __half* Ak =
        A + (long long)blockIdx.z * sAk + (long long)blockIdx.y * 128 * Kdim;
    const __half* Bk =
        Wt + (long long)blockIdx.z * sWk + (long long)blockIdx.x * BN * Kdim;

    const int NTK = Kdim >> 6;  // K chunks of 64 fp16

    auto load_A_chunk = [&](int s, int kt) {
        const unsigned offA = sb + s * STAGE;
        const int ko = kt << 6;
#pragma unroll
        for (int i = 0; i < A_IT; i++) {
            int c = tid + i * NTH;
            int r = c >> 3, q = c & 7;
            cpa16(offA + swz((unsigned)(r * 128 + q * 16)),
                  Ak + (long long)r * Kdim + ko + q * 8);
        }
    };
    auto load_B_half = [&](int s, int kt, int half) {
        const unsigned offB = sb + s * STAGE + ATILE;
        const int ko = kt << 6;
#pragma unroll
        for (int i = 0; i < BH; i++) {
            int c = tid + (half * BH + i) * NTH;
            int r = c >> 3, q = c & 7;
            cpa16(offB + swz((unsigned)(r * 128 + q * 16)),
                  Bk + (long long)r * Kdim + ko + q * 8);
        }
    };

    // per-thread ldmatrix base offsets (relative to tile base, pre-swizzle)
    const int lrow = lane & 15;                         // row within 16 (m or n)
    const unsigned lkb = (unsigned)((lane >> 4) * 16);  // k-half granule (bytes)
    const unsigned aBase = (unsigned)((warp_m * WM + lrow) * 128) + lkb;
    const unsigned bBase = (unsigned)((warp_n * WN + lrow) * 128) + lkb;

    unsigned afr[MT][4], bfr[NT][4];
    float acc[MT][N8][4];
#pragma unroll
    for (int mt = 0; mt < MT; mt++)
#pragma unroll
        for (int j = 0; j < N8; j++)
#pragma unroll
            for (int e = 0; e < 4; e++) acc[mt][j][e] = 0.f;

    // prologue: fill stages 0, 1
    load_A_chunk(0, 0); load_B_half(0, 0, 0); load_B_half(0, 0, 1); cpa_commit();
    load_A_chunk(1, 1); load_B_half(1, 1, 0); load_B_half(1, 1, 1); cpa_commit();

    for (int kt = 0; kt < NTK; ++kt) {
        if (kt + 1 < NTK) cpa_wait<1>(); else cpa_wait<0>();
        __syncthreads();  // stage kt visible; all warps done with slot kt+2's prior life

        const unsigned sA = sb + (kt % STAGES) * STAGE;
        const unsigned sB = sA + ATILE;
        const bool pf = (kt + 2 < NTK);
        const int ps = (kt + 2) % STAGES;

#pragma unroll
        for (int k16 = 0; k16 < 4; k16++) {
            // fragments for this k16 (latency covered by 4 warps/SMSP + cp.async below)
#pragma unroll
            for (int mt = 0; mt < MT; mt++)
                ldsm4(afr[mt][0], afr[mt][1], afr[mt][2], afr[mt][3],
                      sA + swz(aBase + (unsigned)(mt * 2048 + k16 * 32)));
#pragma unroll
            for (int nt = 0; nt < NT; nt++)
                ldsm4(bfr[nt][0], bfr[nt][1], bfr[nt][2], bfr[nt][3],
                      sB + swz(bBase + (unsigned)(nt * 2048 + k16 * 32)));
            // spread the cp.async issue of stage kt+2 across k16 steps;
            // sits between ldsm and mma to widen the dependency gap
            if (pf) {
                if (k16 == 0) load_A_chunk(ps, kt + 2);
                else if (k16 == 1) load_B_half(ps, kt + 2, 0);
                else if (k16 == 2) load_B_half(ps, kt + 2, 1);
                else cpa_commit();
            }
#pragma unroll
            for (int nt = 0; nt < NT; nt++) {
#pragma unroll
                for (int mt = 0; mt < MT; mt++) {
                    mma16816(acc[mt][2 * nt],     afr[mt], bfr[nt][0], bfr[nt][2]);
                    mma16816(acc[mt][2 * nt + 1], afr[mt], bfr[nt][1], bfr[nt][3]);
                }
            }
        }
    }

    // ---- epilogue: bias + (relu) + store ----
    const int r = lane >> 2;        // 0..7
    const int cq = (lane & 3) * 2;  // 0,2,4,6
    const float* bp = bias + (long long)blockIdx.z * sBk + (long long)blockIdx.x * BN +
                      warp_n * WN + cq;
    float2 bv[N8];
#pragma unroll
    for (int j = 0; j < N8; j++) bv[j] = *reinterpret_cast<const float2*>(bp + j * 8);

    const long long obase =
        (long long)blockIdx.z * sOk +
        ((long long)blockIdx.y * 128 + warp_m * WM + r) * (long long)ldo +
        (long long)blockIdx.x * BN + warp_n * WN + cq;

#pragma unroll
    for (int mt = 0; mt < MT; mt++) {
        const long long ro0 = obase + (long long)(mt * 16) * ldo;
        const long long ro1 = ro0 + 8LL * ldo;
#pragma unroll
        for (int j = 0; j < N8; j++) {
            float v00 = acc[mt][j][0] + bv[j].x;
            float v01 = acc[mt][j][1] + bv[j].y;
            float v10 = acc[mt][j][2] + bv[j].x;
            float v11 = acc[mt][j][3] + bv[j].y;
            if (RELU) {
                v00 = fmaxf(v00, 0.f); v01 = fmaxf(v01, 0.f);
                v10 = fmaxf(v10, 0.f); v11 = fmaxf(v11, 0.f);
            }
            if (OUT_F16) {
                __half* ob = reinterpret_cast<__half*>(Out);
                *reinterpret_cast<__half2*>(ob + ro0 + j * 8) = __floats2half2_rn(v00, v01);
                *reinterpret_cast<__half2*>(ob + ro1 + j * 8) = __floats2half2_rn(v10, v11);
            } else {
                float* of = reinterpret_cast<float*>(Out);
                *reinterpret_cast<float2*>(of + ro0 + j * 8) = make_float2(v00, v01);
                *reinterpret_cast<float2*>(of + ro1 + j * 8) = make_float2(v10, v11);
            }
        }
    }
}

// ---------------------------------------------------------------------------
// Launch
// ---------------------------------------------------------------------------
extern "C" void kernel_launch(void* const* d_in, const int* in_sizes, int n_in,
                              void* d_out, int out_size) {
    (void)in_sizes; (void)n_in; (void)out_size;
    const float* x     = (const float*)d_in[0];
    const float* W_in  = (const float*)d_in[1];
    const float* b_in  = (const float*)d_in[2];
    const float* W_hid = (const float*)d_in[3];
    const float* b_hid = (const float*)d_in[4];
    const float* W_out = (const float*)d_in[5];
    const float* b_out = (const float*)d_in[6];
    float* out = (float*)d_out;

    __half *xb, *wtin, *wthid, *wtout, *a0, *a1;
    float *bpad, *lg;
    cudaGetSymbolAddress((void**)&xb, g_xb);
    cudaGetSymbolAddress((void**)&wtin, g_wt_in);
    cudaGetSymbolAddress((void**)&wthid, g_wt_hid);
    cudaGetSymbolAddress((void**)&wtout, g_wt_out);
    cudaGetSymbolAddress((void**)&bpad, g_bout_pad);
    cudaGetSymbolAddress((void**)&a0, g_act0);
    cudaGetSymbolAddress((void**)&a1, g_act1);
    cudaGetSymbolAddress((void**)&lg, g_logits);

    constexpr int SMEM256 = 1024 + 3 * (128 * 128 + 256 * 128);  // 148480
    constexpr int SMEM128 = 1024 + 3 * (128 * 128 + 128 * 128);  // 99328
    cudaFuncSetAttribute((const void*)gemm_ens<256, 4, 4, true, true>,
                         cudaFuncAttributeMaxDynamicSharedMemorySize, SMEM256);
    cudaFuncSetAttribute((const void*)gemm_ens<128, 4, 2, false, false>,
                         cudaFuncAttributeMaxDynamicSharedMemorySize, SMEM128);

    // ---- prep (2 launches) ----
    constexpr int NPREP = BB * FF / 2 + KK * CPAD;
    prep_misc<<<(NPREP + 255) / 256, 256>>>(x, xb, b_out, bpad);
    transpose_all<<<dim3(32, 32, 160), dim3(32, 8)>>>(W_in, wtin, W_hid, wthid, W_out, wtout);

    // ---- L0: [4096,512] x [512,1024] per k -> act0 (relu, fp16) ----
    gemm_ens<256, 4, 4, true, true><<<dim3(HH / 256, BB / 128, KK), 512, SMEM256>>>(
        xb, 0LL, FF,
        wtin, (long long)HH * FF,
        b_in, (long long)HH,
        a0, (long long)BB * HH, HH);

    // ---- L1..L3: hidden layers, ping-pong act0/act1 ----
    for (int i = 0; i < NL; i++) {
        __half* src = (i & 1) ? a1 : a0;
        __half* dst = (i & 1) ? a0 : a1;
        gemm_ens<256, 4, 4, true, true><<<dim3(HH / 256, BB / 128, KK), 512, SMEM256>>>(
            src, (long long)BB * HH, HH,
            wthid + (long long)i * KK * HH * HH, (long long)HH * HH,
            b_hid + (long long)i * KK * HH, (long long)HH,
            dst, (long long)BB * HH, HH);
    }
    // after i=0: a0->a1; i=1: a1->a0; i=2: a0->a1  => final act in a1

    // ---- L4: [4096,1024] x [1024,128pad] per k -> f32 logits (no relu) ----
    gemm_ens<128, 4, 2, false, false><<<dim3(1, BB / 128, KK), 256, SMEM128>>>(
        a1, (long long)BB * HH, HH,
        wtout, (long long)CPAD * HH,
        bpad, (long long)CPAD,
        lg, (long long)BB * CPAD, CPAD);

    // ---- mean over ensemble ----
    reduce_mean_kernel<<<(BB * CC + 255) / 256, 256>>>(lg, out);
}

// round 16
// speedup vs baseline: 1.0251x; 1.0002x over previous
#include <cuda_runtime.h>
#include <cuda_fp16.h>

// ---------------------------------------------------------------------------
// TabM packed ensemble: out = mean_k( MLP_k(x) ), K=32 MLPs 512->1024^4->100.
// Plain sm_103 target: mma.sync.m16n8k16 fp16 (fp32 accum), cp.async 3-stage
// pipeline. R15: 16 warps x (32x64) warp tiles (occ 12.4%->25%) instead of
// 8 x (64x64); single-buffered fragments to fit the 128-reg cap @512 thr.
// ---------------------------------------------------------------------------

#define DI static __device__ __forceinline__

constexpr int BB = 4096;   // batch
constexpr int FF = 512;    // in features
constexpr int HH = 1024;   // hidden
constexpr int CC = 100;    // classes
constexpr int KK = 32;     // ensemble
constexpr int NL = 3;      // hidden->hidden layers
constexpr int CPAD = 128;  // padded classes

// ---- device scratch (__device__ globals: the sanctioned no-alloc path) ----
__device__ __half g_xb[BB * FF];                // x in fp16
__device__ __half g_wt_in[KK * HH * FF];        // W_in^T  [k][h][f]  (K-major)
__device__ __half g_wt_hid[NL * KK * HH * HH];  // W_hid^T [i][k][j][h]
__device__ __half g_wt_out[KK * CPAD * HH];     // W_out^T [k][c_pad][h], zero-padded
__device__ float  g_bout_pad[KK * CPAD];
__device__ __half g_act0[KK * BB * HH];
__device__ __half g_act1[KK * BB * HH];
__device__ float  g_logits[KK * BB * CPAD];     // per-k fp32 logits (padded)

// ---------------------------------------------------------------------------
// PTX helpers (sm_80+ baseline ISA only)
// ---------------------------------------------------------------------------
DI unsigned smem_u32(const void* p) { return (unsigned)__cvta_generic_to_shared(p); }

DI void cpa16(unsigned dst, const void* src) {
    asm volatile("cp.async.cg.shared.global [%0], [%1], 16;"
                 ::"r"(dst), "l"(__cvta_generic_to_global(src)) : "memory");
}
DI void cpa_commit() { asm volatile("cp.async.commit_group;" ::: "memory"); }
template <int N>
DI void cpa_wait() { asm volatile("cp.async.wait_group %0;" ::"n"(N) : "memory"); }

DI unsigned swz(unsigned off) { return off ^ ((off >> 3) & 0x70); }  // SW128 / Swizzle<3,4,3>

DI void ldsm4(unsigned& r0, unsigned& r1, unsigned& r2, unsigned& r3, unsigned addr) {
    asm volatile("ldmatrix.sync.aligned.m8n8.x4.shared.b16 {%0,%1,%2,%3}, [%4];"
                 : "=r"(r0), "=r"(r1), "=r"(r2), "=r"(r3) : "r"(addr));
}

DI void mma16816(float* c, const unsigned* a, unsigned b0, unsigned b1) {
    asm volatile(
        "mma.sync.aligned.m16n8k16.row.col.f32.f16.f16.f32 "
        "{%0,%1,%2,%3}, {%4,%5,%6,%7}, {%8,%9}, {%0,%1,%2,%3};"
        : "+f"(c[0]), "+f"(c[1]), "+f"(c[2]), "+f"(c[3])
        : "r"(a[0]), "r"(a[1]), "r"(a[2]), "r"(a[3]), "r"(b0), "r"(b1));
}

// ---------------------------------------------------------------------------
// Prep kernels (2 launches)
// ---------------------------------------------------------------------------
__global__ void prep_misc(const float* __restrict__ x, __half* __restrict__ xb,
                          const float* __restrict__ bo, float* __restrict__ bpad) {
    constexpr int N1 = BB * FF / 2;
    int i = blockIdx.x * blockDim.x + threadIdx.x;
    if (i < N1) {
        float2 v = reinterpret_cast<const float2*>(x)[i];
        reinterpret_cast<__half2*>(xb)[i] = __floats2half2_rn(v.x, v.y);
    } else {
        int j = i - N1;
        if (j < KK * CPAD) {
            int k = j >> 7, c = j & 127;
            bpad[j] = (c < CC) ? bo[k * CC + c] : 0.f;
        }
    }
}

// transpose_all: all weight transposes in ONE launch (see R14 comment).
__global__ void transpose_all(const float* __restrict__ W_in, __half* __restrict__ wtin,
                              const float* __restrict__ W_hid, __half* __restrict__ wthid,
                              const float* __restrict__ W_out, __half* __restrict__ wtout) {
    __shared__ float t[32][33];
    int z = blockIdx.z;
    const float* ip; __half* op; int R, Cin, Npad;
    if (z < 32) {
        R = FF; Cin = HH; Npad = HH;
        ip = W_in + (long long)z * FF * HH;
        op = wtin + (long long)z * HH * FF;
    } else if (z < 128) {
        R = HH; Cin = HH; Npad = HH;
        ip = W_hid + (long long)(z - 32) * HH * HH;
        op = wthid + (long long)(z - 32) * HH * HH;
    } else {
        R = HH; Cin = CC; Npad = CPAD;
        ip = W_out + (long long)(z - 128) * HH * CC;
        op = wtout + (long long)(z - 128) * CPAD * HH;
    }
    int r0 = blockIdx.x << 5, c0 = blockIdx.y << 5;
    if (r0 >= R || c0 >= Npad) return;
    int tx = threadIdx.x;
#pragma unroll
    for (int dy = threadIdx.y; dy < 32; dy += 8) {
        int cc = c0 + tx;
        t[dy][tx] = (cc < Cin) ? ip[(long long)(r0 + dy) * Cin + cc] : 0.f;
    }
    __syncthreads();
#pragma unroll
    for (int dy = threadIdx.y; dy < 32; dy += 8) {
        op[(long long)(c0 + dy) * R + r0 + tx] = __float2half_rn(t[tx][dy]);
    }
}

__global__ void reduce_mean_kernel(const float* __restrict__ lg, float* __restrict__ out) {
    int i = blockIdx.x * blockDim.x + threadIdx.x;
    if (i >= BB * CC) return;
    int b = i / CC, c = i - b * CC;
    float s = 0.f;
#pragma unroll
    for (int k = 0; k < KK; k++) s += lg[((long long)k * BB + b) * CPAD + c];
    out[i] = s * (1.0f / KK);
}

// ---------------------------------------------------------------------------
// HMMA GEMM:  D[128, BN] = A[128, Kd] @ Wt[BN, Kd]^T  (+bias, relu)
// A row-major (K-major), Wt row-major [n][k] (K-major). Kd % 64 == 0.
// grid: (Ntot/BN, BB/128, KK). NWM x NWN warp grid, warp tile (128/NWM)x(BN/NWN).
// ---------------------------------------------------------------------------
template <int BN, int NWM, int NWN, bool RELU, bool OUT_F16>
__global__ void __launch_bounds__(32 * NWM * NWN) gemm_ens(
    const __half* __restrict__ A, long long sAk, int Kdim,
    const __half* __restrict__ Wt, long long sWk,
    const float* __restrict__ bias, long long sBk,
    void* __restrict__ Out, long long sOk, int ldo) {
    extern __shared__ __align__(1024) char smem_raw[];
    unsigned sb0 = smem_u32(smem_raw);
    const unsigned sb = (sb0 + 1023u) & ~1023u;  // 1024-align keeps swizzle analysis exact

    constexpr int NTH = 32 * NWM * NWN;
    constexpr int WM = 128 / NWM;     // warp tile M
    constexpr int WN = BN / NWN;      // warp tile N
    constexpr int MT = WM / 16;       // A ldmatrix tiles per warp
    constexpr int NT = WN / 16;       // B ldmatrix tiles per warp
    constexpr int N8 = WN / 8;        // n8 mma tiles per warp
    constexpr int ATILE = 128 * 128;  // bytes per A stage
    constexpr int BTILE = BN * 128;   // bytes per B stage
    constexpr int STAGE = ATILE + BTILE;
    constexpr int STAGES = 3;
    constexpr int A_IT = 1024 / NTH;      // A 16B-granule iterations
    constexpr int B_IT = (BN * 8) / NTH;  // B 16B-granule iterations
    constexpr int BH = B_IT / 2;

    const int tid = threadIdx.x;
    const int lane = tid & 31;
    const int wid = tid >> 5;
    const int warp_m = wid % NWM;
    const int warp_n = wid / NWM;

    const __half* Ak =
        A + (long long)blockIdx.z * sAk + (long long)blockIdx.y * 128 * Kdim;
    const __half* Bk =
        Wt + (long long)blockIdx.z * sWk + (long long)blockIdx.x * BN * Kdim;

    const int NTK = Kdim >> 6;  // K chunks of 64 fp16

    auto load_A_chunk = [&](int s, int kt) {
        const unsigned offA = sb + s * STAGE;
        const int ko = kt << 6;
#pragma unroll
        for (int i = 0; i < A_IT; i++) {
            int c = tid + i * NTH;
            int r = c >> 3, q = c & 7;
            cpa16(offA + swz((unsigned)(r * 128 + q * 16)),
                  Ak + (long long)r * Kdim + ko + q * 8);
        }
    };
    auto load_B_half = [&](int s, int kt, int half) {
        const unsigned offB = sb + s * STAGE + ATILE;
        const int ko = kt << 6;
#pragma unroll
        for (int i = 0; i < BH; i++) {
            int c = tid + (half * BH + i) * NTH;
            int r = c >> 3, q = c & 7;
            cpa16(offB + swz((unsigned)(r * 128 + q * 16)),
                  Bk + (long long)r * Kdim + ko + q * 8);
        }
    };

    // per-thread ldmatrix base offsets (relative to tile base, pre-swizzle)
    const int lrow = lane & 15;                         // row within 16 (m or n)
    const unsigned lkb = (unsigned)((lane >> 4) * 16);  // k-half granule (bytes)
    const unsigned aBase = (unsigned)((warp_m * WM + lrow) * 128) + lkb;
    const unsigned bBase = (unsigned)((warp_n * WN + lrow) * 128) + lkb;

    unsigned afr[MT][4], bfr[NT][4];
    float acc[MT][N8][4];
#pragma unroll
    for (int mt = 0; mt < MT; mt++)
#pragma unroll
        for (int j = 0; j < N8; j++)
#pragma unroll
            for (int e = 0; e < 4; e++) acc[mt][j][e] = 0.f;

    // prologue: fill stages 0, 1
    load_A_chunk(0, 0); load_B_half(0, 0, 0); load_B_half(0, 0, 1); cpa_commit();
    load_A_chunk(1, 1); load_B_half(1, 1, 0); load_B_half(1, 1, 1); cpa_commit();

    for (int kt = 0; kt < NTK; ++kt) {
        if (kt + 1 < NTK) cpa_wait<1>(); else cpa_wait<0>();
        __syncthreads();  // stage kt visible; all warps done with slot kt+2's prior life

        const unsigned sA = sb + (kt % STAGES) * STAGE;
        const unsigned sB = sA + ATILE;
        const bool pf = (kt + 2 < NTK);
        const int ps = (kt + 2) % STAGES;

#pragma unroll
        for (int k16 = 0; k16 < 4; k16++) {
            // fragments for this k16 (latency covered by 4 warps/SMSP + cp.async below)
#pragma unroll
            for (int mt = 0; mt < MT; mt++)
                ldsm4(afr[mt][0], afr[mt][1], afr[mt][2], afr[mt][3],
                      sA + swz(aBase + (unsigned)(mt * 2048 + k16 * 32)));
#pragma unroll
            for (int nt = 0; nt < NT; nt++)
                ldsm4(bfr[nt][0], bfr[nt][1], bfr[nt][2], bfr[nt][3],
                      sB + swz(bBase + (unsigned)(nt * 2048 + k16 * 32)));
            // spread the cp.async issue of stage kt+2 across k16 steps;
            // sits between ldsm and mma to widen the dependency gap
            if (pf) {
                if (k16 == 0) load_A_chunk(ps, kt + 2);
                else if (k16 == 1) load_B_half(ps, kt + 2, 0);
                else if (k16 == 2) load_B_half(ps, kt + 2, 1);
                else cpa_commit();
            }
#pragma unroll
            for (int nt = 0; nt < NT; nt++) {
#pragma unroll
                for (int mt = 0; mt < MT; mt++) {
                    mma16816(acc[mt][2 * nt],     afr[mt], bfr[nt][0], bfr[nt][2]);
                    mma16816(acc[mt][2 * nt + 1], afr[mt], bfr[nt][1], bfr[nt][3]);
                }
            }
        }
    }

    // ---- epilogue: bias + (relu) + store ----
    const int r = lane >> 2;        // 0..7
    const int cq = (lane & 3) * 2;  // 0,2,4,6
    const float* bp = bias + (long long)blockIdx.z * sBk + (long long)blockIdx.x * BN +
                      warp_n * WN + cq;
    float2 bv[N8];
#pragma unroll
    for (int j = 0; j < N8; j++) bv[j] = *reinterpret_cast<const float2*>(bp + j * 8);

    const long long obase =
        (long long)blockIdx.z * sOk +
        ((long long)blockIdx.y * 128 + warp_m * WM + r) * (long long)ldo +
        (long long)blockIdx.x * BN + warp_n * WN + cq;

#pragma unroll
    for (int mt = 0; mt < MT; mt++) {
        const long long ro0 = obase + (long long)(mt * 16) * ldo;
        const long long ro1 = ro0 + 8LL * ldo;
#pragma unroll
        for (int j = 0; j < N8; j++) {
            float v00 = acc[mt][j][0] + bv[j].x;
            float v01 = acc[mt][j][1] + bv[j].y;
            float v10 = acc[mt][j][2] + bv[j].x;
            float v11 = acc[mt][j][3] + bv[j].y;
            if (RELU) {
                v00 = fmaxf(v00, 0.f); v01 = fmaxf(v01, 0.f);
                v10 = fmaxf(v10, 0.f); v11 = fmaxf(v11, 0.f);
            }
            if (OUT_F16) {
                __half* ob = reinterpret_cast<__half*>(Out);
                *reinterpret_cast<__half2*>(ob + ro0 + j * 8) = __floats2half2_rn(v00, v01);
                *reinterpret_cast<__half2*>(ob + ro1 + j * 8) = __floats2half2_rn(v10, v11);
            } else {
                float* of = reinterpret_cast<float*>(Out);
                *reinterpret_cast<float2*>(of + ro0 + j * 8) = make_float2(v00, v01);
                *reinterpret_cast<float2*>(of + ro1 + j * 8) = make_float2(v10, v11);
            }
        }
    }
}

// ---------------------------------------------------------------------------
// Launch
// ---------------------------------------------------------------------------
extern "C" void kernel_launch(void* const* d_in, const int* in_sizes, int n_in,
                              void* d_out, int out_size) {
    (void)in_sizes; (void)n_in; (void)out_size;
    const float* x     = (const float*)d_in[0];
    const float* W_in  = (const float*)d_in[1];
    const float* b_in  = (const float*)d_in[2];
    const float* W_hid = (const float*)d_in[3];
    const float* b_hid = (const float*)d_in[4];
    const float* W_out = (const float*)d_in[5];
    const float* b_out = (const float*)d_in[6];
    float* out = (float*)d_out;

    __half *xb, *wtin, *wthid, *wtout, *a0, *a1;
    float *bpad, *lg;
    cudaGetSymbolAddress((void**)&xb, g_xb);
    cudaGetSymbolAddress((void**)&wtin, g_wt_in);
    cudaGetSymbolAddress((void**)&wthid, g_wt_hid);
    cudaGetSymbolAddress((void**)&wtout, g_wt_out);
    cudaGetSymbolAddress((void**)&bpad, g_bout_pad);
    cudaGetSymbolAddress((void**)&a0, g_act0);
    cudaGetSymbolAddress((void**)&a1, g_act1);
    cudaGetSymbolAddress((void**)&lg, g_logits);

    constexpr int SMEM256 = 1024 + 3 * (128 * 128 + 256 * 128);  // 148480
    constexpr int SMEM128 = 1024 + 3 * (128 * 128 + 128 * 128);  // 99328
    cudaFuncSetAttribute((const void*)gemm_ens<256, 4, 4, true, true>,
                         cudaFuncAttributeMaxDynamicSharedMemorySize, SMEM256);
    cudaFuncSetAttribute((const void*)gemm_ens<128, 4, 2, false, false>,
                         cudaFuncAttributeMaxDynamicSharedMemorySize, SMEM128);

    // ---- prep (2 launches) ----
    constexpr int NPREP = BB * FF / 2 + KK * CPAD;
    prep_misc<<<(NPREP + 255) / 256, 256>>>(x, xb, b_out, bpad);
    transpose_all<<<dim3(32, 32, 160), dim3(32, 8)>>>(W_in, wtin, W_hid, wthid, W_out, wtout);

    // ---- L0: [4096,512] x [512,1024] per k -> act0 (relu, fp16) ----
    gemm_ens<256, 4, 4, true, true><<<dim3(HH / 256, BB / 128, KK), 512, SMEM256>>>(
        xb, 0LL, FF,
        wtin, (long long)HH * FF,
        b_in, (long long)HH,
        a0, (long long)BB * HH, HH);

    // ---- L1..L3: hidden layers, ping-pong act0/act1 ----
    for (int i = 0; i < NL; i++) {
        __half* src = (i & 1) ? a1 : a0;
        __half* dst = (i & 1) ? a0 : a1;
        gemm_ens<256, 4, 4, true, true><<<dim3(HH / 256, BB / 128, KK), 512, SMEM256>>>(
            src, (long long)BB * HH, HH,
            wthid + (long long)i * KK * HH * HH, (long long)HH * HH,
            b_hid + (long long)i * KK * HH, (long long)HH,
            dst, (long long)BB * HH, HH);
    }
    // after i=0: a0->a1; i=1: a1->a0; i=2: a0->a1  => final act in a1

    // ---- L4: [4096,1024] x [1024,128pad] per k -> f32 logits (no relu) ----
    gemm_ens<128, 4, 2, false, false><<<dim3(1, BB / 128, KK), 256, SMEM128>>>(
        a1, (long long)BB * HH, HH,
        wtout, (long long)CPAD * HH,
        bpad, (long long)CPAD,
        lg, (long long)BB * CPAD, CPAD);

    // ---- mean over ensemble ----
    reduce_mean_kernel<<<(BB * CC + 255) / 256, 256>>>(lg, out);
}